// round 2
// baseline (speedup 1.0000x reference)
#include <cuda_runtime.h>
#include <math.h>

// Problem constants
#define T_STEPS 16384
#define HID     1024
#define INP     256
#define NLAB    32

#define NCTA    128          // persistent CTAs, one per SM, single wave
#define WPC     8            // warps per CTA; NCTA*WPC == HID rows (1 warp : 1 row)
#define TPB     (WPC * 32)   // 256

// Tagged hidden state: word = (float_bits(h) << 32) | step_tag.
// Double-buffered by step parity. Reset kernel restores tags each launch so
// graph replays are deterministic. No other sync state exists.
__device__ unsigned long long g_hbuf[2][HID];

__device__ __forceinline__ unsigned long long ldx(const unsigned long long* p) {
    unsigned long long v;
    asm volatile("ld.relaxed.gpu.global.b64 %0, [%1];" : "=l"(v) : "l"(p));
    return v;
}
__device__ __forceinline__ void stx(unsigned long long* p, unsigned long long v) {
    asm volatile("st.relaxed.gpu.global.b64 [%0], %1;" :: "l"(p), "l"(v) : "memory");
}
__device__ __forceinline__ unsigned long long packh(float h, unsigned tag) {
    return ((unsigned long long)__float_as_uint(h) << 32) | (unsigned long long)tag;
}
__device__ __forceinline__ float unpackh(unsigned long long v) {
    return __uint_as_float((unsigned)(v >> 32));
}

__global__ void rnn_reset_kernel() {
    int t = threadIdx.x;
    unsigned long long z = packh(0.0f, 0u);   // h0 = 0, tag 0
    for (int i = t; i < 2 * HID; i += blockDim.x)
        ((unsigned long long*)g_hbuf)[i] = z;
}

__global__ void __launch_bounds__(TPB, 1) rnn_scan_kernel(
    const float* __restrict__ X,    // [T, 1, 256]
    const float* __restrict__ Wi,   // [1024, 256]
    const float* __restrict__ bi,   // [1024]
    const float* __restrict__ Wh,   // [1024, 1024]
    const float* __restrict__ bh,   // [1024]
    const float* __restrict__ Wo,   // [32, 1024]
    const float* __restrict__ bo,   // [32]
    float* __restrict__ out)        // [32] log-softmax
{
    const int t    = threadIdx.x;
    const int lane = t & 31;
    const int warp = t >> 5;
    const int row  = blockIdx.x * WPC + warp;   // this warp's hidden row

    // ---- Register-resident weights (held for all 16384 steps) ----
    // Lane l owns columns {l + 32k}: 32 Wh weights, 8 Wi weights.
    float w[32];
    #pragma unroll
    for (int k = 0; k < 32; k++) w[k] = Wh[row * HID + lane + 32 * k];
    float wi[8];
    #pragma unroll
    for (int k = 0; k < 8; k++) wi[k] = Wi[row * INP + lane + 32 * k];
    const float bias = bi[row] + bh[row];

    // x for step 0
    float x[8];
    #pragma unroll
    for (int k = 0; k < 8; k++) x[k] = X[lane + 32 * k];

    for (int s = 0; s < T_STEPS; s++) {
        // Prefetch next step's input slice (independent of h).
        float xn[8];
        #pragma unroll
        for (int k = 0; k < 8; k++) xn[k] = 0.0f;
        if (s + 1 < T_STEPS) {
            #pragma unroll
            for (int k = 0; k < 8; k++) xn[k] = X[(s + 1) * INP + lane + 32 * k];
        }

        // Issue all 32 tagged-h polls up front (pipelined L2 loads).
        const unsigned long long* hb = g_hbuf[s & 1];
        unsigned long long vv[32];
        #pragma unroll
        for (int k = 0; k < 32; k++) vv[k] = ldx(hb + lane + 32 * k);

        // Input projection while polls are in flight.
        float a0 = 0.f, a1 = 0.f, a2 = 0.f, a3 = 0.f;
        a0 = fmaf(wi[0], x[0], a0);  a1 = fmaf(wi[1], x[1], a1);
        a2 = fmaf(wi[2], x[2], a2);  a3 = fmaf(wi[3], x[3], a3);
        a0 = fmaf(wi[4], x[4], a0);  a1 = fmaf(wi[5], x[5], a1);
        a2 = fmaf(wi[6], x[6], a2);  a3 = fmaf(wi[7], x[7], a3);

        // Resolve tags: retry only stale words. Tags in this buffer are
        // always <= s (proof in commit msg), so equality == ready.
        const unsigned tag = (unsigned)s;
        for (;;) {
            unsigned bad = 0;
            #pragma unroll
            for (int k = 0; k < 32; k++) bad |= ((unsigned)vv[k]) ^ tag;
            if (bad == 0) break;
            #pragma unroll
            for (int k = 0; k < 32; k++)
                if (((unsigned)vv[k]) != tag) vv[k] = ldx(hb + lane + 32 * k);
        }

        // Recurrent GEMV partials.
        #pragma unroll
        for (int k = 0; k < 32; k += 4) {
            a0 = fmaf(w[k + 0], unpackh(vv[k + 0]), a0);
            a1 = fmaf(w[k + 1], unpackh(vv[k + 1]), a1);
            a2 = fmaf(w[k + 2], unpackh(vv[k + 2]), a2);
            a3 = fmaf(w[k + 3], unpackh(vv[k + 3]), a3);
        }
        float acc = (a0 + a1) + (a2 + a3);

        // In-warp butterfly reduce; no shared memory, no bar.sync.
        #pragma unroll
        for (int off = 16; off > 0; off >>= 1)
            acc += __shfl_xor_sync(0xffffffffu, acc, off);

        if (lane == 0) {
            float hnew = tanhf(acc + bias);
            stx(&g_hbuf[(s + 1) & 1][row], packh(hnew, (unsigned)(s + 1)));
        }

        #pragma unroll
        for (int k = 0; k < 8; k++) x[k] = xn[k];
    }

    // ---- Epilogue: CTA 0 computes logits + log_softmax on h_T ----
    if (blockIdx.x == 0) {
        __shared__ float sh[HID];
        for (int j = t; j < HID; j += TPB) {
            unsigned long long v = ldx(&g_hbuf[0][j]);   // T even -> buffer 0
            while (((unsigned)v) != (unsigned)T_STEPS) v = ldx(&g_hbuf[0][j]);
            sh[j] = unpackh(v);
        }
        __syncthreads();

        int orow = t >> 3;      // 32 rows x 8 threads
        int sub  = t & 7;
        float acc = 0.0f;
        #pragma unroll 4
        for (int j = 0; j < HID / 8; j += 4) {
            int col = sub * (HID / 8) + j;
            float4 w4 = ((const float4*)Wo)[(orow * HID + col) >> 2];
            acc = fmaf(w4.x, sh[col + 0], acc);
            acc = fmaf(w4.y, sh[col + 1], acc);
            acc = fmaf(w4.z, sh[col + 2], acc);
            acc = fmaf(w4.w, sh[col + 3], acc);
        }
        acc += __shfl_down_sync(0xffffffffu, acc, 4);
        acc += __shfl_down_sync(0xffffffffu, acc, 2);
        acc += __shfl_down_sync(0xffffffffu, acc, 1);

        __shared__ float s_log[NLAB];
        if (sub == 0 && orow < NLAB) s_log[orow] = acc + bo[orow];
        __syncthreads();

        if (t < NLAB) {
            float v = s_log[t];
            float m = v;
            #pragma unroll
            for (int off = 16; off > 0; off >>= 1)
                m = fmaxf(m, __shfl_xor_sync(0xffffffffu, m, off));
            float e = expf(v - m);
            float ssum = e;
            #pragma unroll
            for (int off = 16; off > 0; off >>= 1)
                ssum += __shfl_xor_sync(0xffffffffu, ssum, off);
            out[t] = v - m - logf(ssum);
        }
    }
}

extern "C" void kernel_launch(void* const* d_in, const int* in_sizes, int n_in,
                              void* d_out, int out_size) {
    const float* X  = (const float*)d_in[0];
    const float* Wi = (const float*)d_in[1];
    const float* bi = (const float*)d_in[2];
    const float* Wh = (const float*)d_in[3];
    const float* bh = (const float*)d_in[4];
    const float* Wo = (const float*)d_in[5];
    const float* bo = (const float*)d_in[6];
    float* out = (float*)d_out;

    rnn_reset_kernel<<<1, 256>>>();
    rnn_scan_kernel<<<NCTA, TPB>>>(X, Wi, bi, Wh, bh, Wo, bo, out);
}

// round 3
// speedup vs baseline: 7.6360x; 7.6360x over previous
#include <cuda_runtime.h>
#include <math.h>

// Problem constants
#define T_STEPS 16384
#define HID     1024
#define INP     256
#define NLAB    32

#define NCTA    128          // persistent CTAs, one per SM, single wave
#define WPC     8            // warps per CTA; NCTA*WPC == HID rows (1 warp : 1 row)
#define TPB     (WPC * 32)   // 256
#define WPT     (HID / TPB)  // tagged words polled per thread = 4

// Tagged hidden state: word = (float_bits(h) << 32) | step_tag.
// Double-buffered by step parity. Reset kernel restores tags each launch so
// graph replays are deterministic. Publication is a single relaxed 64-bit
// store (value+tag travel atomically) -> no fences anywhere in the scan.
__device__ unsigned long long g_hbuf[2][HID];

__device__ __forceinline__ unsigned long long ldx(const unsigned long long* p) {
    unsigned long long v;
    asm volatile("ld.relaxed.gpu.global.b64 %0, [%1];" : "=l"(v) : "l"(p));
    return v;
}
__device__ __forceinline__ void stx(unsigned long long* p, unsigned long long v) {
    asm volatile("st.relaxed.gpu.global.b64 [%0], %1;" :: "l"(p), "l"(v) : "memory");
}
__device__ __forceinline__ unsigned long long packh(float h, unsigned tag) {
    return ((unsigned long long)__float_as_uint(h) << 32) | (unsigned long long)tag;
}
__device__ __forceinline__ float unpackh(unsigned long long v) {
    return __uint_as_float((unsigned)(v >> 32));
}

__global__ void rnn_reset_kernel() {
    int t = threadIdx.x;
    unsigned long long z = packh(0.0f, 0u);   // h0 = 0, tag 0
    for (int i = t; i < 2 * HID; i += blockDim.x)
        ((unsigned long long*)g_hbuf)[i] = z;
}

__global__ void __launch_bounds__(TPB, 1) rnn_scan_kernel(
    const float* __restrict__ X,    // [T, 1, 256]
    const float* __restrict__ Wi,   // [1024, 256]
    const float* __restrict__ bi,   // [1024]
    const float* __restrict__ Wh,   // [1024, 1024]
    const float* __restrict__ bh,   // [1024]
    const float* __restrict__ Wo,   // [32, 1024]
    const float* __restrict__ bo,   // [32]
    float* __restrict__ out)        // [32] log-softmax
{
    const int t    = threadIdx.x;
    const int lane = t & 31;
    const int warp = t >> 5;
    const int row  = blockIdx.x * WPC + warp;   // this warp's hidden row

    // Double-buffered plain-float h staged per CTA. One barrier per step.
    __shared__ float sh[2][HID];

    // ---- Register-resident weights (held for all 16384 steps) ----
    // Lane l owns columns {l + 32k}: 32 Wh weights, 8 Wi weights.
    float w[32];
    #pragma unroll
    for (int k = 0; k < 32; k++) w[k] = Wh[row * HID + lane + 32 * k];
    float wi[8];
    #pragma unroll
    for (int k = 0; k < 8; k++) wi[k] = Wi[row * INP + lane + 32 * k];
    const float bias = bi[row] + bh[row];

    // x for step 0
    float x[8];
    #pragma unroll
    for (int k = 0; k < 8; k++) x[k] = X[lane + 32 * k];

    for (int s = 0; s < T_STEPS; s++) {
        const int buf = s & 1;
        const unsigned tag = (unsigned)s;
        const unsigned long long* hb = g_hbuf[buf];

        // ---- Poll phase: this CTA reads global h exactly once (8KB). ----
        // Thread t owns words {t + 256*i}. Issue all 4 loads, retry stale only.
        unsigned long long v[WPT];
        #pragma unroll
        for (int i = 0; i < WPT; i++) v[i] = ldx(hb + t + TPB * i);

        // Prefetch next step's input slice while polls are in flight.
        float xn[8];
        #pragma unroll
        for (int k = 0; k < 8; k++) xn[k] = 0.0f;
        if (s + 1 < T_STEPS) {
            #pragma unroll
            for (int k = 0; k < 8; k++) xn[k] = X[(s + 1) * INP + lane + 32 * k];
        }

        for (;;) {
            unsigned bad = 0;
            #pragma unroll
            for (int i = 0; i < WPT; i++) bad |= ((unsigned)v[i]) ^ tag;
            if (bad == 0) break;
            #pragma unroll
            for (int i = 0; i < WPT; i++)
                if (((unsigned)v[i]) != tag) v[i] = ldx(hb + t + TPB * i);
        }
        #pragma unroll
        for (int i = 0; i < WPT; i++) sh[buf][t + TPB * i] = unpackh(v[i]);

        __syncthreads();   // the only barrier per step

        // ---- Compute phase: warp computes its row from SMEM h. ----
        float a0, a1, a2, a3;
        a0 = wi[0] * x[0];  a1 = wi[1] * x[1];
        a2 = wi[2] * x[2];  a3 = wi[3] * x[3];
        a0 = fmaf(wi[4], x[4], a0);  a1 = fmaf(wi[5], x[5], a1);
        a2 = fmaf(wi[6], x[6], a2);  a3 = fmaf(wi[7], x[7], a3);

        const float* hs = sh[buf];
        #pragma unroll
        for (int k = 0; k < 32; k += 4) {
            a0 = fmaf(w[k + 0], hs[lane + 32 * (k + 0)], a0);
            a1 = fmaf(w[k + 1], hs[lane + 32 * (k + 1)], a1);
            a2 = fmaf(w[k + 2], hs[lane + 32 * (k + 2)], a2);
            a3 = fmaf(w[k + 3], hs[lane + 32 * (k + 3)], a3);
        }
        float acc = (a0 + a1) + (a2 + a3);

        #pragma unroll
        for (int off = 16; off > 0; off >>= 1)
            acc += __shfl_xor_sync(0xffffffffu, acc, off);

        if (lane == 0) {
            float hnew = tanhf(acc + bias);
            stx(&g_hbuf[buf ^ 1][row], packh(hnew, tag + 1u));
        }

        #pragma unroll
        for (int k = 0; k < 8; k++) x[k] = xn[k];
    }

    // ---- Epilogue: CTA 0 computes logits + log_softmax on h_T ----
    if (blockIdx.x == 0) {
        for (int j = t; j < HID; j += TPB) {
            unsigned long long vv = ldx(&g_hbuf[0][j]);   // T even -> buffer 0
            while (((unsigned)vv) != (unsigned)T_STEPS) vv = ldx(&g_hbuf[0][j]);
            sh[0][j] = unpackh(vv);
        }
        __syncthreads();

        int orow = t >> 3;      // 32 rows x 8 threads
        int sub  = t & 7;
        float acc = 0.0f;
        #pragma unroll 4
        for (int j = 0; j < HID / 8; j += 4) {
            int col = sub * (HID / 8) + j;
            float4 w4 = ((const float4*)Wo)[(orow * HID + col) >> 2];
            acc = fmaf(w4.x, sh[0][col + 0], acc);
            acc = fmaf(w4.y, sh[0][col + 1], acc);
            acc = fmaf(w4.z, sh[0][col + 2], acc);
            acc = fmaf(w4.w, sh[0][col + 3], acc);
        }
        acc += __shfl_down_sync(0xffffffffu, acc, 4);
        acc += __shfl_down_sync(0xffffffffu, acc, 2);
        acc += __shfl_down_sync(0xffffffffu, acc, 1);

        __shared__ float s_log[NLAB];
        if (sub == 0 && orow < NLAB) s_log[orow] = acc + bo[orow];
        __syncthreads();

        if (t < NLAB) {
            float vl = s_log[t];
            float m = vl;
            #pragma unroll
            for (int off = 16; off > 0; off >>= 1)
                m = fmaxf(m, __shfl_xor_sync(0xffffffffu, m, off));
            float e = expf(vl - m);
            float ssum = e;
            #pragma unroll
            for (int off = 16; off > 0; off >>= 1)
                ssum += __shfl_xor_sync(0xffffffffu, ssum, off);
            out[t] = vl - m - logf(ssum);
        }
    }
}

extern "C" void kernel_launch(void* const* d_in, const int* in_sizes, int n_in,
                              void* d_out, int out_size) {
    const float* X  = (const float*)d_in[0];
    const float* Wi = (const float*)d_in[1];
    const float* bi = (const float*)d_in[2];
    const float* Wh = (const float*)d_in[3];
    const float* bh = (const float*)d_in[4];
    const float* Wo = (const float*)d_in[5];
    const float* bo = (const float*)d_in[6];
    float* out = (float*)d_out;

    rnn_reset_kernel<<<1, 256>>>();
    rnn_scan_kernel<<<NCTA, TPB>>>(X, Wi, bi, Wh, bh, Wo, bo, out);
}

// round 5
// speedup vs baseline: 11.7861x; 1.5435x over previous
#include <cuda_runtime.h>
#include <math.h>

// Problem constants
#define T_STEPS 16384
#define HID     1024
#define INP     256
#define NLAB    32

#define NCTA    128          // persistent CTAs, one per SM, single wave
#define WPC     8            // warps per CTA; NCTA*WPC == HID rows (1 warp : 1 row)
#define TPB     (WPC * 32)   // 256
#define WPT     (HID / TPB)  // tagged words polled per thread = 4

// Tagged hidden state: word = (float_bits(h) << 32) | step_tag.
// Double-buffered by step parity; single relaxed 64-bit store publishes
// value+tag atomically -> no fences anywhere. Reset kernel restores tags each
// launch so graph replays are deterministic.
__device__ unsigned long long g_hbuf[2][HID];

__device__ __forceinline__ unsigned long long ldx(const unsigned long long* p) {
    unsigned long long v;
    asm volatile("ld.relaxed.gpu.global.b64 %0, [%1];" : "=l"(v) : "l"(p));
    return v;
}
__device__ __forceinline__ void stx(unsigned long long* p, unsigned long long v) {
    asm volatile("st.relaxed.gpu.global.b64 [%0], %1;" :: "l"(p), "l"(v) : "memory");
}
__device__ __forceinline__ unsigned long long packh(float h, unsigned tag) {
    return ((unsigned long long)__float_as_uint(h) << 32) | (unsigned long long)tag;
}
__device__ __forceinline__ float unpackh(unsigned long long v) {
    return __uint_as_float((unsigned)(v >> 32));
}
__device__ __forceinline__ float tanh_fast(float v) {
    float r;
    asm volatile("tanh.approx.f32 %0, %1;" : "=f"(r) : "f"(v));
    return r;
}

__global__ void rnn_reset_kernel() {
    int t = threadIdx.x;
    unsigned long long z = packh(0.0f, 0u);   // h0 = 0, tag 0
    for (int i = t; i < 2 * HID; i += blockDim.x)
        ((unsigned long long*)g_hbuf)[i] = z;
}

__global__ void __launch_bounds__(TPB, 1) rnn_scan_kernel(
    const float* __restrict__ X,    // [T, 1, 256]
    const float* __restrict__ Wi,   // [1024, 256]
    const float* __restrict__ bi,   // [1024]
    const float* __restrict__ Wh,   // [1024, 1024]
    const float* __restrict__ bh,   // [1024]
    const float* __restrict__ Wo,   // [32, 1024]
    const float* __restrict__ bo,   // [32]
    float* __restrict__ out)        // [32] log-softmax
{
    const int t    = threadIdx.x;
    const int lane = t & 31;
    const int warp = t >> 5;
    const int row  = blockIdx.x * WPC + warp;   // this warp's hidden row

    // Double-buffered plain-float h staged per CTA. One barrier per step.
    __shared__ float sh[2][HID];

    // ---- Register-resident weights (held for all 16384 steps) ----
    // Lane l owns hidden columns (k/4)*128 + 4l + (k%4), k=0..31  (float4-
    // contiguous groups -> 8x LDS.128 per step) and the analogous 8 input cols.
    float w[32];
    #pragma unroll
    for (int k = 0; k < 32; k++)
        w[k] = Wh[row * HID + (k >> 2) * 128 + 4 * lane + (k & 3)];
    float wi[8];
    #pragma unroll
    for (int k = 0; k < 8; k++)
        wi[k] = Wi[row * INP + (k >> 2) * 128 + 4 * lane + (k & 3)];
    const float bias = bi[row] + bh[row];

    // ---- 3-deep input pipeline: x0 = step s, x1 = step s+1 ----
    const float4* X4 = (const float4*)X;   // step s slice at X4[s*64 + ...]
    float4 x0a = X4[lane];            float4 x0b = X4[32 + lane];
    float4 x1a = X4[64 + lane];       float4 x1b = X4[96 + lane];

    for (int s = 0; s < T_STEPS; s++) {
        const int buf = s & 1;
        const unsigned tag = (unsigned)s;
        const unsigned long long* hb = g_hbuf[buf];

        // ---- Poll phase: this CTA reads global h exactly once (8KB). ----
        unsigned long long v[WPT];
        #pragma unroll
        for (int i = 0; i < WPT; i++) v[i] = ldx(hb + t + TPB * i);

        // Prefetch x for step s+2 (two full step-periods to cover DRAM).
        float4 x2a, x2b;
        x2a.x = x2a.y = x2a.z = x2a.w = 0.f;
        x2b = x2a;
        if (s + 2 < T_STEPS) {
            x2a = X4[(s + 2) * 64 + lane];
            x2b = X4[(s + 2) * 64 + 32 + lane];
        }

        // Input projection for THIS step while polls are in flight.
        float a0 = (lane == 0) ? bias : 0.0f;
        float a1 = 0.f, a2 = 0.f, a3 = 0.f;
        a0 = fmaf(wi[0], x0a.x, a0);  a1 = fmaf(wi[1], x0a.y, a1);
        a2 = fmaf(wi[2], x0a.z, a2);  a3 = fmaf(wi[3], x0a.w, a3);
        a0 = fmaf(wi[4], x0b.x, a0);  a1 = fmaf(wi[5], x0b.y, a1);
        a2 = fmaf(wi[6], x0b.z, a2);  a3 = fmaf(wi[7], x0b.w, a3);

        // Resolve tags: retry only stale words (tags monotone, <= s).
        for (;;) {
            unsigned bad = 0;
            #pragma unroll
            for (int i = 0; i < WPT; i++) bad |= ((unsigned)v[i]) ^ tag;
            if (bad == 0) break;
            #pragma unroll
            for (int i = 0; i < WPT; i++)
                if (((unsigned)v[i]) != tag) v[i] = ldx(hb + t + TPB * i);
        }
        #pragma unroll
        for (int i = 0; i < WPT; i++) sh[buf][t + TPB * i] = unpackh(v[i]);

        __syncthreads();   // the only barrier per step

        // ---- Recurrent GEMV: 8x LDS.128 + 32 FMA. ----
        const float* hs = sh[buf];
        #pragma unroll
        for (int g = 0; g < 8; g++) {
            float4 h4 = *(const float4*)(hs + g * 128 + 4 * lane);
            a0 = fmaf(w[4 * g + 0], h4.x, a0);
            a1 = fmaf(w[4 * g + 1], h4.y, a1);
            a2 = fmaf(w[4 * g + 2], h4.z, a2);
            a3 = fmaf(w[4 * g + 3], h4.w, a3);
        }
        float acc = (a0 + a1) + (a2 + a3);
        #pragma unroll
        for (int off = 16; off > 0; off >>= 1)
            acc += __shfl_xor_sync(0xffffffffu, acc, off);

        if (lane == 0) {
            float hnew = tanh_fast(acc);
            stx(&g_hbuf[buf ^ 1][row], packh(hnew, tag + 1u));
        }

        x0a = x1a; x0b = x1b;
        x1a = x2a; x1b = x2b;
    }

    // ---- Epilogue: CTA 0 computes logits + log_softmax on h_T ----
    if (blockIdx.x == 0) {
        for (int j = t; j < HID; j += TPB) {
            unsigned long long vv = ldx(&g_hbuf[0][j]);   // T even -> buffer 0
            while (((unsigned)vv) != (unsigned)T_STEPS) vv = ldx(&g_hbuf[0][j]);
            sh[0][j] = unpackh(vv);
        }
        __syncthreads();

        int orow = t >> 3;      // 32 rows x 8 threads
        int sub  = t & 7;
        float acc = 0.0f;
        #pragma unroll 4
        for (int j = 0; j < HID / 8; j += 4) {
            int col = sub * (HID / 8) + j;
            float4 w4 = ((const float4*)Wo)[(orow * HID + col) >> 2];
            acc = fmaf(w4.x, sh[0][col + 0], acc);
            acc = fmaf(w4.y, sh[0][col + 1], acc);
            acc = fmaf(w4.z, sh[0][col + 2], acc);
            acc = fmaf(w4.w, sh[0][col + 3], acc);
        }
        acc += __shfl_down_sync(0xffffffffu, acc, 4);
        acc += __shfl_down_sync(0xffffffffu, acc, 2);
        acc += __shfl_down_sync(0xffffffffu, acc, 1);

        __shared__ float s_log[NLAB];
        if (sub == 0 && orow < NLAB) s_log[orow] = acc + bo[orow];
        __syncthreads();

        if (t < NLAB) {
            float vl = s_log[t];
            float m = vl;
            #pragma unroll
            for (int off = 16; off > 0; off >>= 1)
                m = fmaxf(m, __shfl_xor_sync(0xffffffffu, m, off));
            float e = expf(vl - m);
            float ssum = e;
            #pragma unroll
            for (int off = 16; off > 0; off >>= 1)
                ssum += __shfl_xor_sync(0xffffffffu, ssum, off);
            out[t] = vl - m - logf(ssum);
        }
    }
}

extern "C" void kernel_launch(void* const* d_in, const int* in_sizes, int n_in,
                              void* d_out, int out_size) {
    const float* X  = (const float*)d_in[0];
    const float* Wi = (const float*)d_in[1];
    const float* bi = (const float*)d_in[2];
    const float* Wh = (const float*)d_in[3];
    const float* bh = (const float*)d_in[4];
    const float* Wo = (const float*)d_in[5];
    const float* bo = (const float*)d_in[6];
    float* out = (float*)d_out;

    rnn_reset_kernel<<<1, 256>>>();
    rnn_scan_kernel<<<NCTA, TPB>>>(X, Wi, bi, Wh, bh, Wo, bo, out);
}